// round 7
// baseline (speedup 1.0000x reference)
#include <cuda_runtime.h>
#include <cuda_bf16.h>
#include <cstdint>

// Problem dims
#define MDIM 256
#define TDIM 512
#define NXDIM 256
#define UDIM 256

// Scratch for x-projections: 3 matrices x [T][M][U] fp32 = 402 MB.
// Layout per matrix: xp[((t*256 + m)*256) + u]  (linear in GEMM row g = t*256+m)
#define XP_STRIDE (33554432ULL) // 512*256*256
__device__ float g_xp[3ULL * XP_STRIDE];

// ---------------- packed f32x2 helpers ----------------
#define FFMA2(c_, a_, b_) \
    asm volatile("fma.rn.f32x2 %0, %1, %2, %0;" : "+l"(c_) : "l"(a_), "l"(b_))

__device__ __forceinline__ unsigned long long dup2(float a) {
    unsigned long long r;
    asm("mov.b64 %0, {%1, %1};" : "=l"(r) : "f"(a));
    return r;
}
__device__ __forceinline__ void unpack2(float& lo, float& hi, unsigned long long v) {
    asm("mov.b64 {%0, %1}, %2;" : "=f"(lo), "=f"(hi) : "l"(v));
}

// =====================================================================
// Phase 1: x projections.  C[g, n] = sum_k x_row(g)[k] * W[k][n]
//   g = t*256 + m  (so output is linear: xp + g*256 + n)
//   x row base = x + (m*T + t)*NX
// Tiles: BM=128, BN=128, BK=16.  grid = (1024, 2, 3), block = 256.
//   blockIdx.z: 0 -> wux (xu), 1 -> wrx (xr), 2 -> wcx (xc)
// =====================================================================
__global__ __launch_bounds__(256, 1)
void xproj_kernel(const float* __restrict__ x,
                  const float* __restrict__ w_u,
                  const float* __restrict__ w_r,
                  const float* __restrict__ w_c)
{
    const float* __restrict__ w =
        (blockIdx.z == 0) ? w_u : ((blockIdx.z == 1) ? w_r : w_c);
    float* __restrict__ outp = g_xp + (size_t)blockIdx.z * XP_STRIDE;

    const int tid = threadIdx.x;
    const int g0  = blockIdx.x * 128;
    const int t   = g0 >> 8;        // fixed for the whole tile (128 | 256)
    const int m0  = g0 & 255;       // 0 or 128
    const int n0  = blockIdx.y * 128;

    __shared__ float As[16][132];   // [k][m], padded
    __shared__ float Bs[16][128];   // [k][n]

    const int tx = tid & 15;        // 0..15 -> 8 cols each
    const int ty = tid >> 4;        // 0..15 -> 8 rows each

    unsigned long long acc[8][4];
    #pragma unroll
    for (int i = 0; i < 8; i++)
        #pragma unroll
        for (int j = 0; j < 4; j++) acc[i][j] = 0ULL;

    for (int kk = 0; kk < NXDIM; kk += 16) {
        // ---- load A tile (128 rows x 16 k), transposed into As[k][m] ----
        #pragma unroll
        for (int l = 0; l < 2; l++) {
            int f  = tid + l * 256;
            int i  = f >> 2;                 // row 0..127
            int kv = (f & 3) * 4;            // k sub-chunk
            const float4 v = *(const float4*)(x +
                ((size_t)(m0 + i) * TDIM + t) * NXDIM + kk + kv);
            As[kv + 0][i] = v.x;
            As[kv + 1][i] = v.y;
            As[kv + 2][i] = v.z;
            As[kv + 3][i] = v.w;
        }
        // ---- load B tile (16 k x 128 n) ----
        #pragma unroll
        for (int l = 0; l < 2; l++) {
            int f  = tid + l * 256;
            int k  = f >> 5;                 // 0..15
            int nn = (f & 31) * 4;
            *(float4*)&Bs[k][nn] =
                *(const float4*)(w + (size_t)(kk + k) * UDIM + n0 + nn);
        }
        __syncthreads();

        #pragma unroll
        for (int k = 0; k < 16; k++) {
            float4 a0v = *(const float4*)&As[k][ty * 8];
            float4 a1v = *(const float4*)&As[k][ty * 8 + 4];
            const unsigned long long* bp =
                (const unsigned long long*)&Bs[k][tx * 8];
            unsigned long long b0 = bp[0], b1 = bp[1], b2 = bp[2], b3 = bp[3];
            float av[8] = {a0v.x, a0v.y, a0v.z, a0v.w,
                           a1v.x, a1v.y, a1v.z, a1v.w};
            #pragma unroll
            for (int i = 0; i < 8; i++) {
                unsigned long long ad = dup2(av[i]);
                FFMA2(acc[i][0], ad, b0);
                FFMA2(acc[i][1], ad, b1);
                FFMA2(acc[i][2], ad, b2);
                FFMA2(acc[i][3], ad, b3);
            }
        }
        __syncthreads();
    }

    // ---- epilogue: write C (biases are added in phase 2) ----
    #pragma unroll
    for (int i = 0; i < 8; i++) {
        int g = g0 + ty * 8 + i;
        float o[8];
        unpack2(o[0], o[1], acc[i][0]);
        unpack2(o[2], o[3], acc[i][1]);
        unpack2(o[4], o[5], acc[i][2]);
        unpack2(o[6], o[7], acc[i][3]);
        float* op = outp + (size_t)g * UDIM + n0 + tx * 8;
        *(float4*)(op)     = make_float4(o[0], o[1], o[2], o[3]);
        *(float4*)(op + 4) = make_float4(o[4], o[5], o[6], o[7]);
    }
}

// =====================================================================
// Phase 2: sequential GRU scan.
// 64 CTAs x 4 batch rows; 256 threads, thread n owns output unit n for
// its 4 rows.  State c kept in registers (c_reg[4]) + broadcast smem
// copy c_s laid out [k][row] so row pairs are natural f32x2 operands.
// Weights streamed from L2 (resident: 768 KB << 126 MB, shared by all CTAs).
// =====================================================================
__device__ __forceinline__ float sigmoid_f(float z) {
    return 1.0f / (1.0f + __expf(-z));
}

__global__ __launch_bounds__(256, 1)
void gru_scan_kernel(const float* __restrict__ wuc,
                     const float* __restrict__ wrc,
                     const float* __restrict__ wcc,
                     const float* __restrict__ bu,
                     const float* __restrict__ br,
                     const float* __restrict__ bc,
                     const float* __restrict__ a0,
                     float* __restrict__ out)
{
    __shared__ float c_s[UDIM * 4];   // [k][r]
    __shared__ float h_s[UDIM * 4];   // [k][r]

    const int n  = threadIdx.x;       // output unit
    const int r0 = blockIdx.x * 4;    // first batch row

    const float* __restrict__ xu = g_xp;
    const float* __restrict__ xr = g_xp + XP_STRIDE;
    const float* __restrict__ xc = g_xp + 2ULL * XP_STRIDE;

    const float bun = bu[n];
    const float brn = br[n];
    const float bcn = bc[n];

    float c_reg[4];
    #pragma unroll
    for (int r = 0; r < 4; r++)
        c_reg[r] = a0[(size_t)(r0 + r) * UDIM + n];
    *(float4*)&c_s[n * 4] = make_float4(c_reg[0], c_reg[1], c_reg[2], c_reg[3]);
    __syncthreads();

    for (int t = 0; t < TDIM; t++) {
        // prefetch x projections for this step (hidden under phase-A GEMV)
        const size_t xb = ((size_t)t * MDIM + r0) * UDIM + n;
        float xu_[4], xr_[4], xc_[4];
        #pragma unroll
        for (int r = 0; r < 4; r++) {
            xu_[r] = __ldg(xu + xb + (size_t)r * UDIM);
            xr_[r] = __ldg(xr + xb + (size_t)r * UDIM);
            xc_[r] = __ldg(xc + xb + (size_t)r * UDIM);
        }

        // ---- phase A: pre_u = c @ wuc[:,n], pre_r = c @ wrc[:,n] ----
        unsigned long long au01 = 0ULL, au23 = 0ULL, ar01 = 0ULL, ar23 = 0ULL;
        #pragma unroll 16
        for (int k = 0; k < UDIM; k++) {
            unsigned long long a01 = *(const unsigned long long*)&c_s[k * 4];
            unsigned long long a23 = *(const unsigned long long*)&c_s[k * 4 + 2];
            unsigned long long wu = dup2(__ldg(&wuc[k * UDIM + n]));
            unsigned long long wr = dup2(__ldg(&wrc[k * UDIM + n]));
            FFMA2(au01, a01, wu);
            FFMA2(au23, a23, wu);
            FFMA2(ar01, a01, wr);
            FFMA2(ar23, a23, wr);
        }
        float pu[4], pr[4];
        unpack2(pu[0], pu[1], au01);
        unpack2(pu[2], pu[3], au23);
        unpack2(pr[0], pr[1], ar01);
        unpack2(pr[2], pr[3], ar23);

        float gu[4], h[4];
        #pragma unroll
        for (int r = 0; r < 4; r++) {
            gu[r]      = sigmoid_f(pu[r] + xu_[r] + bun);
            float grr  = sigmoid_f(pr[r] + xr_[r] + brn);
            h[r]       = grr * c_reg[r];
        }
        *(float4*)&h_s[n * 4] = make_float4(h[0], h[1], h[2], h[3]);
        __syncthreads();

        // ---- phase B: pre_c = (g_r*c) @ wcc[:,n] ----
        unsigned long long ac01 = 0ULL, ac23 = 0ULL;
        #pragma unroll 16
        for (int k = 0; k < UDIM; k++) {
            unsigned long long a01 = *(const unsigned long long*)&h_s[k * 4];
            unsigned long long a23 = *(const unsigned long long*)&h_s[k * 4 + 2];
            unsigned long long wc = dup2(__ldg(&wcc[k * UDIM + n]));
            FFMA2(ac01, a01, wc);
            FFMA2(ac23, a23, wc);
        }
        float pc[4];
        unpack2(pc[0], pc[1], ac01);
        unpack2(pc[2], pc[3], ac23);

        #pragma unroll
        for (int r = 0; r < 4; r++) {
            float cand = tanhf(pc[r] + xc_[r] + bcn);
            // c_new = gu*cand + (1-gu)*c
            c_reg[r] = fmaf(gu[r], cand - c_reg[r], c_reg[r]);
        }
        // All threads are past phase A (sync above), so c_s can be rewritten.
        *(float4*)&c_s[n * 4] = make_float4(c_reg[0], c_reg[1], c_reg[2], c_reg[3]);
        __syncthreads();
    }

    #pragma unroll
    for (int r = 0; r < 4; r++)
        out[(size_t)(r0 + r) * UDIM + n] = c_reg[r];
}

// =====================================================================
// Launch
// Inputs (metadata order):
//  0:x [256,512,256]  1:a0 [256,256]
//  2:wcx 3:wcc 4:bc   5:wux 6:wuc 7:bu   8:wrx 9:wrc 10:br
// =====================================================================
extern "C" void kernel_launch(void* const* d_in, const int* in_sizes, int n_in,
                              void* d_out, int out_size)
{
    const float* x   = (const float*)d_in[0];
    const float* a0  = (const float*)d_in[1];
    const float* wcx = (const float*)d_in[2];
    const float* wcc = (const float*)d_in[3];
    const float* bc  = (const float*)d_in[4];
    const float* wux = (const float*)d_in[5];
    const float* wuc = (const float*)d_in[6];
    const float* bu  = (const float*)d_in[7];
    const float* wrx = (const float*)d_in[8];
    const float* wrc = (const float*)d_in[9];
    const float* br  = (const float*)d_in[10];
    float* out = (float*)d_out;

    // Phase 1: x projections (z=0 -> wux, z=1 -> wrx, z=2 -> wcx)
    dim3 g1((MDIM * TDIM) / 128, UDIM / 128, 3);
    xproj_kernel<<<g1, 256>>>(x, wux, wrx, wcx);

    // Phase 2: sequential scan
    gru_scan_kernel<<<MDIM / 4, 256>>>(wuc, wrc, wcc, bu, br, bc, a0, out);
}

// round 8
// speedup vs baseline: 1.6064x; 1.6064x over previous
#include <cuda_runtime.h>
#include <cuda_bf16.h>
#include <cstdint>

// Problem dims
#define MDIM 256
#define TDIM 512
#define NXDIM 256
#define UDIM 256

// Scratch for x-projections: 3 matrices x [T][M][U] fp32 = 402 MB.
#define XP_STRIDE (33554432ULL) // 512*256*256
__device__ float g_xp[3ULL * XP_STRIDE];

// ---------------- packed f32x2 helpers ----------------
#define FFMA2(c_, a_, b_) \
    asm volatile("fma.rn.f32x2 %0, %1, %2, %0;" : "+l"(c_) : "l"(a_), "l"(b_))

__device__ __forceinline__ unsigned long long dup2(float a) {
    unsigned long long r;
    asm("mov.b64 %0, {%1, %1};" : "=l"(r) : "f"(a));
    return r;
}
__device__ __forceinline__ void unpack2(float& lo, float& hi, unsigned long long v) {
    asm("mov.b64 {%0, %1}, %2;" : "=f"(lo), "=f"(hi) : "l"(v));
}
__device__ __forceinline__ float hsum2(unsigned long long v) {
    float lo, hi; unpack2(lo, hi, v); return lo + hi;
}

// ---------------- cluster / DSMEM helpers ----------------
__device__ __forceinline__ uint32_t smem_u32(const void* p) {
    uint32_t a;
    asm("{ .reg .u64 t; cvta.to.shared.u64 t, %1; cvt.u32.u64 %0, t; }"
        : "=r"(a) : "l"(p));
    return a;
}
__device__ __forceinline__ uint32_t mapa_rank(uint32_t addr, uint32_t rank) {
    uint32_t r;
    asm("mapa.shared::cluster.u32 %0, %1, %2;" : "=r"(r) : "r"(addr), "r"(rank));
    return r;
}
__device__ __forceinline__ void st_cluster_f32(uint32_t addr, float v) {
    asm volatile("st.shared::cluster.f32 [%0], %1;" :: "r"(addr), "f"(v) : "memory");
}
__device__ __forceinline__ uint32_t ctarank() {
    uint32_t r; asm("mov.u32 %0, %%cluster_ctarank;" : "=r"(r)); return r;
}
#define CLUSTER_SYNC_() do { \
    asm volatile("barrier.cluster.arrive.aligned;" ::: "memory"); \
    asm volatile("barrier.cluster.wait.aligned;" ::: "memory"); } while (0)

// =====================================================================
// Phase 1: x projections (unchanged — ~1.06 ms, fma-bound).
// C[g, n] = sum_k x_row(g)[k] * W[k][n],  g = t*256 + m
// =====================================================================
__global__ __launch_bounds__(256, 1)
void xproj_kernel(const float* __restrict__ x,
                  const float* __restrict__ w_u,
                  const float* __restrict__ w_r,
                  const float* __restrict__ w_c)
{
    const float* __restrict__ w =
        (blockIdx.z == 0) ? w_u : ((blockIdx.z == 1) ? w_r : w_c);
    float* __restrict__ outp = g_xp + (size_t)blockIdx.z * XP_STRIDE;

    const int tid = threadIdx.x;
    const int g0  = blockIdx.x * 128;
    const int t   = g0 >> 8;
    const int m0  = g0 & 255;
    const int n0  = blockIdx.y * 128;

    __shared__ float As[16][132];
    __shared__ float Bs[16][128];

    const int tx = tid & 15;
    const int ty = tid >> 4;

    unsigned long long acc[8][4];
    #pragma unroll
    for (int i = 0; i < 8; i++)
        #pragma unroll
        for (int j = 0; j < 4; j++) acc[i][j] = 0ULL;

    for (int kk = 0; kk < NXDIM; kk += 16) {
        #pragma unroll
        for (int l = 0; l < 2; l++) {
            int f  = tid + l * 256;
            int i  = f >> 2;
            int kv = (f & 3) * 4;
            const float4 v = *(const float4*)(x +
                ((size_t)(m0 + i) * TDIM + t) * NXDIM + kk + kv);
            As[kv + 0][i] = v.x;
            As[kv + 1][i] = v.y;
            As[kv + 2][i] = v.z;
            As[kv + 3][i] = v.w;
        }
        #pragma unroll
        for (int l = 0; l < 2; l++) {
            int f  = tid + l * 256;
            int k  = f >> 5;
            int nn = (f & 31) * 4;
            *(float4*)&Bs[k][nn] =
                *(const float4*)(w + (size_t)(kk + k) * UDIM + n0 + nn);
        }
        __syncthreads();

        #pragma unroll
        for (int k = 0; k < 16; k++) {
            float4 a0v = *(const float4*)&As[k][ty * 8];
            float4 a1v = *(const float4*)&As[k][ty * 8 + 4];
            const unsigned long long* bp =
                (const unsigned long long*)&Bs[k][tx * 8];
            unsigned long long b0 = bp[0], b1 = bp[1], b2 = bp[2], b3 = bp[3];
            float av[8] = {a0v.x, a0v.y, a0v.z, a0v.w,
                           a1v.x, a1v.y, a1v.z, a1v.w};
            #pragma unroll
            for (int i = 0; i < 8; i++) {
                unsigned long long ad = dup2(av[i]);
                FFMA2(acc[i][0], ad, b0);
                FFMA2(acc[i][1], ad, b1);
                FFMA2(acc[i][2], ad, b2);
                FFMA2(acc[i][3], ad, b3);
            }
        }
        __syncthreads();
    }

    #pragma unroll
    for (int i = 0; i < 8; i++) {
        int g = g0 + ty * 8 + i;
        float o[8];
        unpack2(o[0], o[1], acc[i][0]);
        unpack2(o[2], o[3], acc[i][1]);
        unpack2(o[4], o[5], acc[i][2]);
        unpack2(o[6], o[7], acc[i][3]);
        float* op = outp + (size_t)g * UDIM + n0 + tx * 8;
        *(float4*)(op)     = make_float4(o[0], o[1], o[2], o[3]);
        *(float4*)(op + 4) = make_float4(o[4], o[5], o[6], o[7]);
    }
}

// =====================================================================
// Phase 2: sequential GRU scan — cluster-of-4, smem-resident weights.
//   32 clusters x 4 CTAs = 128 CTAs.  Cluster owns 8 batch rows.
//   CTA rank owns 64 n-columns; holds wuc/wrc/wcc slices TRANSPOSED in
//   smem ([n_local][k], row stride 260 for conflict-free LDS128).
//   256 threads: thread = (n_local = tid>>2, rp = tid&3), owns rows
//   rp and rp+4.  f32x2 accumulation pairs over k.
//   Per step: phase A (gates u,r) -> DSMEM-broadcast h -> cluster sync
//   -> phase B (candidate) -> DSMEM-broadcast c_new -> cluster sync.
// =====================================================================
#define WSTRIDE 260
#define SM_WU 0
#define SM_WR (64 * WSTRIDE)           // 16640
#define SM_WC (128 * WSTRIDE)          // 33280
#define SM_C  (192 * WSTRIDE)          // 49920
#define SM_H  (192 * WSTRIDE + 8 * WSTRIDE) // 52000
#define SM_FLOATS (192 * WSTRIDE + 16 * WSTRIDE) // 54080
#define SM_BYTES (SM_FLOATS * 4)       // 216320

__device__ __forceinline__ float sigmoid_f(float z) {
    return 1.0f / (1.0f + __expf(-z));
}

__global__ __launch_bounds__(256, 1) __cluster_dims__(4, 1, 1)
void gru_scan2(const float* __restrict__ wuc,
               const float* __restrict__ wrc,
               const float* __restrict__ wcc,
               const float* __restrict__ bu,
               const float* __restrict__ br,
               const float* __restrict__ bc,
               const float* __restrict__ a0,
               float* __restrict__ out)
{
    extern __shared__ float sm[];
    float* wu_s = sm + SM_WU;
    float* wr_s = sm + SM_WR;
    float* wc_s = sm + SM_WC;
    float* c_s  = sm + SM_C;
    float* h_s  = sm + SM_H;

    const int tid = threadIdx.x;
    const uint32_t rank = ctarank();
    const int n0 = (int)rank * 64;
    const int r0 = (blockIdx.x >> 2) * 8;     // first batch row of cluster

    const int n_l = tid >> 2;
    const int rp  = tid & 3;
    const int ra  = rp, rb = rp + 4;
    const int n_g = n0 + n_l;

    // ---- load weight slices transposed: wT[n_l][k] = W[k][n0+n_l] ----
    #pragma unroll 4
    for (int j = 0; j < 64; j++) {
        int i  = tid + j * 256;
        int k  = i >> 6;
        int nl = i & 63;
        wu_s[nl * WSTRIDE + k] = wuc[k * UDIM + n0 + nl];
        wr_s[nl * WSTRIDE + k] = wrc[k * UDIM + n0 + nl];
        wc_s[nl * WSTRIDE + k] = wcc[k * UDIM + n0 + nl];
    }
    // ---- init c_s (full 8 rows, direct from a0) ----
    for (int i = tid; i < 8 * 256; i += 256) {
        int r = i >> 8, k = i & 255;
        c_s[r * WSTRIDE + k] = a0[(size_t)(r0 + r) * UDIM + k];
    }
    float c_a = a0[(size_t)(r0 + ra) * UDIM + n_g];
    float c_b = a0[(size_t)(r0 + rb) * UDIM + n_g];
    const float bun = bu[n_g], brn = br[n_g], bcn = bc[n_g];

    // ---- precompute remote DSMEM store addresses (broadcast targets) ----
    uint32_t h_a_loc = smem_u32(&h_s[ra * WSTRIDE + n_g]);
    uint32_t h_b_loc = smem_u32(&h_s[rb * WSTRIDE + n_g]);
    uint32_t c_a_loc = smem_u32(&c_s[ra * WSTRIDE + n_g]);
    uint32_t c_b_loc = smem_u32(&c_s[rb * WSTRIDE + n_g]);
    uint32_t h_a_r[4], h_b_r[4], c_a_r[4], c_b_r[4];
    #pragma unroll
    for (int d = 0; d < 4; d++) {
        h_a_r[d] = mapa_rank(h_a_loc, d);
        h_b_r[d] = mapa_rank(h_b_loc, d);
        c_a_r[d] = mapa_rank(c_a_loc, d);
        c_b_r[d] = mapa_rank(c_b_loc, d);
    }

    __syncthreads();
    CLUSTER_SYNC_();

    const float* __restrict__ xu = g_xp;
    const float* __restrict__ xr = g_xp + XP_STRIDE;
    const float* __restrict__ xc = g_xp + 2ULL * XP_STRIDE;

    const float* wup = wu_s + n_l * WSTRIDE;
    const float* wrp = wr_s + n_l * WSTRIDE;
    const float* wcp = wc_s + n_l * WSTRIDE;
    const float* cap = c_s + ra * WSTRIDE;
    const float* cbp = c_s + rb * WSTRIDE;
    const float* hap = h_s + ra * WSTRIDE;
    const float* hbp = h_s + rb * WSTRIDE;

    for (int t = 0; t < TDIM; t++) {
        // prefetch x-projection terms for this step (hidden under phase A)
        const size_t xb = ((size_t)t * MDIM + r0) * UDIM + n_g;
        const float xu_a = __ldg(xu + xb + (size_t)ra * UDIM);
        const float xu_b = __ldg(xu + xb + (size_t)rb * UDIM);
        const float xr_a = __ldg(xr + xb + (size_t)ra * UDIM);
        const float xr_b = __ldg(xr + xb + (size_t)rb * UDIM);
        const float xc_a = __ldg(xc + xb + (size_t)ra * UDIM);
        const float xc_b = __ldg(xc + xb + (size_t)rb * UDIM);

        // ---- phase A: pre_u, pre_r for rows ra, rb ----
        unsigned long long aUa0 = 0, aUa1 = 0, aUb0 = 0, aUb1 = 0;
        unsigned long long aRa0 = 0, aRa1 = 0, aRb0 = 0, aRb1 = 0;
        #pragma unroll 8
        for (int k = 0; k < UDIM; k += 4) {
            ulonglong2 wu4 = *(const ulonglong2*)(wup + k);
            ulonglong2 wr4 = *(const ulonglong2*)(wrp + k);
            ulonglong2 ca4 = *(const ulonglong2*)(cap + k);
            ulonglong2 cb4 = *(const ulonglong2*)(cbp + k);
            FFMA2(aUa0, ca4.x, wu4.x); FFMA2(aUa1, ca4.y, wu4.y);
            FFMA2(aUb0, cb4.x, wu4.x); FFMA2(aUb1, cb4.y, wu4.y);
            FFMA2(aRa0, ca4.x, wr4.x); FFMA2(aRa1, ca4.y, wr4.y);
            FFMA2(aRb0, cb4.x, wr4.x); FFMA2(aRb1, cb4.y, wr4.y);
        }
        const float gu_a = sigmoid_f(hsum2(aUa0) + hsum2(aUa1) + xu_a + bun);
        const float gu_b = sigmoid_f(hsum2(aUb0) + hsum2(aUb1) + xu_b + bun);
        const float gr_a = sigmoid_f(hsum2(aRa0) + hsum2(aRa1) + xr_a + brn);
        const float gr_b = sigmoid_f(hsum2(aRb0) + hsum2(aRb1) + xr_b + brn);
        const float h_a = gr_a * c_a;
        const float h_b = gr_b * c_b;

        // broadcast h to all 4 CTAs
        #pragma unroll
        for (int d = 0; d < 4; d++) {
            st_cluster_f32(h_a_r[d], h_a);
            st_cluster_f32(h_b_r[d], h_b);
        }
        CLUSTER_SYNC_();

        // ---- phase B: pre_c = (g_r*c) @ wcc[:, n] ----
        unsigned long long aCa0 = 0, aCa1 = 0, aCb0 = 0, aCb1 = 0;
        #pragma unroll 8
        for (int k = 0; k < UDIM; k += 4) {
            ulonglong2 wc4 = *(const ulonglong2*)(wcp + k);
            ulonglong2 ha4 = *(const ulonglong2*)(hap + k);
            ulonglong2 hb4 = *(const ulonglong2*)(hbp + k);
            FFMA2(aCa0, ha4.x, wc4.x); FFMA2(aCa1, ha4.y, wc4.y);
            FFMA2(aCb0, hb4.x, wc4.x); FFMA2(aCb1, hb4.y, wc4.y);
        }
        const float cand_a = tanhf(hsum2(aCa0) + hsum2(aCa1) + xc_a + bcn);
        const float cand_b = tanhf(hsum2(aCb0) + hsum2(aCb1) + xc_b + bcn);
        c_a = fmaf(gu_a, cand_a - c_a, c_a);
        c_b = fmaf(gu_b, cand_b - c_b, c_b);

        // broadcast c_new to all 4 CTAs
        #pragma unroll
        for (int d = 0; d < 4; d++) {
            st_cluster_f32(c_a_r[d], c_a);
            st_cluster_f32(c_b_r[d], c_b);
        }
        CLUSTER_SYNC_();
    }

    out[(size_t)(r0 + ra) * UDIM + n_g] = c_a;
    out[(size_t)(r0 + rb) * UDIM + n_g] = c_b;
}

// =====================================================================
// Launch
// Inputs (metadata order):
//  0:x [256,512,256]  1:a0 [256,256]
//  2:wcx 3:wcc 4:bc   5:wux 6:wuc 7:bu   8:wrx 9:wrc 10:br
// =====================================================================
extern "C" void kernel_launch(void* const* d_in, const int* in_sizes, int n_in,
                              void* d_out, int out_size)
{
    const float* x   = (const float*)d_in[0];
    const float* a0  = (const float*)d_in[1];
    const float* wcx = (const float*)d_in[2];
    const float* wcc = (const float*)d_in[3];
    const float* bc  = (const float*)d_in[4];
    const float* wux = (const float*)d_in[5];
    const float* wuc = (const float*)d_in[6];
    const float* bu  = (const float*)d_in[7];
    const float* wrx = (const float*)d_in[8];
    const float* wrc = (const float*)d_in[9];
    const float* br  = (const float*)d_in[10];
    float* out = (float*)d_out;

    // Opt in to 211 KB dynamic smem for the scan kernel (idempotent).
    cudaFuncSetAttribute(gru_scan2,
                         cudaFuncAttributeMaxDynamicSharedMemorySize, SM_BYTES);

    // Phase 1: x projections (z=0 -> wux, z=1 -> wrx, z=2 -> wcx)
    dim3 g1((MDIM * TDIM) / 128, UDIM / 128, 3);
    xproj_kernel<<<g1, 256>>>(x, wux, wrx, wcx);

    // Phase 2: sequential scan — 32 clusters x 4 CTAs
    gru_scan2<<<128, 256, SM_BYTES>>>(wuc, wrc, wcc, bu, br, bc, a0, out);
}